// round 5
// baseline (speedup 1.0000x reference)
#include <cuda_runtime.h>
#include <cstddef>

// Problem constants (fixed by the dataset)
#define DD 16     // ds_dim
#define NN 32     // number of systems
#define HH 128    // gating hidden width
#define THREADS 512

typedef unsigned long long ull;

// ---- f32x2 packed-math helpers (sm_103a) ----
__device__ __forceinline__ ull pack2(float lo, float hi) {
    ull r; asm("mov.b64 %0, {%1,%2};" : "=l"(r) : "f"(lo), "f"(hi)); return r;
}
__device__ __forceinline__ ull dup2(float v) { return pack2(v, v); }
__device__ __forceinline__ void unpack2(ull v, float& lo, float& hi) {
    asm("mov.b64 {%0,%1}, %2;" : "=f"(lo), "=f"(hi) : "l"(v));
}
__device__ __forceinline__ ull fma2(ull a, ull b, ull c) {
    ull d; asm("fma.rn.f32x2 %0, %1, %2, %3;" : "=l"(d) : "l"(a), "l"(b), "l"(c));
    return d;
}

// Dynamic smem layout (floats):
//   sW1t2 [H*D]   -W1, transposed+packed over j-pairs:
//                 float idx jp*32 + d*2 + half = -W1[(2jp+half)*D + d]
//                 (as ull[jp][d]: {j=2jp, j=2jp+1} packed)
//   sW2t  [H*N]   transposed: sW2t[j*N + n] = W2[n*H + j]
//   sA    [N*D*D] transposed A: sA[n*256 + d*16 + k] = (B+C)[n][k][d]
//   sb1p  [H]     b1'[j] = b1[j] + sum_d W1[j][d]*xt[d]  (consumed as j-pairs)
//   sb2   [N]
//   sxt   [D]
//   swb   [N*THREADS]  per-thread normalized softmax weights
#define W_FLOATS (HH*DD + HH*NN + NN*DD*DD + HH + NN + DD)
#define SMEM_FLOATS (W_FLOATS + NN*THREADS)

__global__ __launch_bounds__(THREADS)
void fused_gated_ds_kernel(
    const float* __restrict__ x_cur,
    const float* __restrict__ W1,
    const float* __restrict__ b1,
    const float* __restrict__ W2,
    const float* __restrict__ b2,
    const float* __restrict__ Bm,
    const float* __restrict__ Cm,
    const float* __restrict__ xt,
    float* __restrict__ out,
    int Btot)
{
    extern __shared__ float smem[];
    float* sW1t2 = smem;                    // 2048
    float* sW2t  = sW1t2 + HH*DD;           // 4096
    float* sA    = sW2t  + HH*NN;           // 8192
    float* sb1p  = sA    + NN*DD*DD;        // 128
    float* sb2   = sb1p  + HH;              // 32
    float* sxt   = sb2   + NN;              // 16
    float* swb   = smem + W_FLOATS;         // 16384

    const int tid = threadIdx.x;

    // ---- stage weights ----
    // -W1 transposed/packed over j-pairs
    for (int i = tid; i < HH*DD; i += THREADS) {
        int jp = i / (2*DD);
        int r  = i % (2*DD);
        int d  = r >> 1, half = r & 1;
        sW1t2[i] = -W1[(2*jp + half)*DD + d];
    }
    for (int i = tid; i < HH*NN; i += THREADS) {
        int j = i / NN, n = i % NN;
        sW2t[i] = W2[n*HH + j];
    }
    for (int i = tid; i < NN*DD*DD; i += THREADS) {
        int n = i / (DD*DD);
        int r = i % (DD*DD);
        int d = r / DD, k = r % DD;
        int src = n*DD*DD + k*DD + d;       // A[n][k][d] -> sA[n][d][k]
        sA[i] = Bm[src] + Cm[src];
    }
    if (tid < NN) sb2[tid] = b2[tid];
    if (tid < DD) sxt[tid] = xt[tid];
    __syncthreads();

    // b1'[j] = b1[j] + sum_d W1[j][d]*xt[d]  (use gmem W1, no extra smem dep)
    if (tid < HH) {
        float s = b1[tid];
        #pragma unroll
        for (int d = 0; d < DD; d++) s += W1[tid*DD + d] * sxt[d];
        sb1p[tid] = s;
    }
    __syncthreads();

    const int row = blockIdx.x * THREADS + tid;
    if (row >= Btot) return;

    // ---- diffd[d] = dup2(xt[d] - x[d]) ; x never stored ----
    ull diffd[DD];
    {
        const float4* xg = reinterpret_cast<const float4*>(x_cur + (size_t)row * DD);
        #pragma unroll
        for (int q = 0; q < 4; q++) {
            float4 v = xg[q];
            diffd[4*q+0] = dup2(sxt[4*q+0] - v.x);
            diffd[4*q+1] = dup2(sxt[4*q+1] - v.y);
            diffd[4*q+2] = dup2(sxt[4*q+2] - v.z);
            diffd[4*q+3] = dup2(sxt[4*q+3] - v.w);
        }
    }

    // ---- logits packed over n pairs ----
    ull Lp[16];
    {
        const ulonglong2* b2p = reinterpret_cast<const ulonglong2*>(sb2);
        #pragma unroll
        for (int q = 0; q < 8; q++) {
            ulonglong2 v = b2p[q];
            Lp[2*q] = v.x; Lp[2*q+1] = v.y;
        }
    }

    // ---- fused GEMM1 (j-pair packed, bias-folded, relu) + GEMM2 ----
    #pragma unroll 4
    for (int jp = 0; jp < HH/2; jp++) {
        const ulonglong2* w1p = reinterpret_cast<const ulonglong2*>(sW1t2 + jp*2*DD);
        ull acc = *reinterpret_cast<const ull*>(sb1p + 2*jp);  // {b1'[2jp], b1'[2jp+1]}
        #pragma unroll
        for (int t = 0; t < 8; t++) {
            ulonglong2 wv = w1p[t];
            acc = fma2(wv.x, diffd[2*t],   acc);
            acc = fma2(wv.y, diffd[2*t+1], acc);
        }
        float h0, h1; unpack2(acc, h0, h1);
        const ull hd0 = dup2(fmaxf(h0, 0.0f));
        const ull hd1 = dup2(fmaxf(h1, 0.0f));

        const ulonglong2* w2a = reinterpret_cast<const ulonglong2*>(sW2t + (2*jp)*NN);
        const ulonglong2* w2b = reinterpret_cast<const ulonglong2*>(sW2t + (2*jp+1)*NN);
        #pragma unroll
        for (int q = 0; q < 8; q++) {
            ulonglong2 wv = w2a[q];
            Lp[2*q]   = fma2(wv.x, hd0, Lp[2*q]);
            Lp[2*q+1] = fma2(wv.y, hd0, Lp[2*q+1]);
        }
        #pragma unroll
        for (int q = 0; q < 8; q++) {
            ulonglong2 wv = w2b[q];
            Lp[2*q]   = fma2(wv.x, hd1, Lp[2*q]);
            Lp[2*q+1] = fma2(wv.y, hd1, Lp[2*q+1]);
        }
    }

    // ---- softmax; store normalized weights to SMEM (Lp dies here) ----
    {
        float ev[NN];
        #pragma unroll
        for (int i = 0; i < 16; i++) unpack2(Lp[i], ev[2*i], ev[2*i+1]);
        float m = ev[0];
        #pragma unroll
        for (int n = 1; n < NN; n++) m = fmaxf(m, ev[n]);
        float s = 0.0f;
        #pragma unroll
        for (int n = 0; n < NN; n++) { ev[n] = __expf(ev[n] - m); s += ev[n]; }
        const float inv = 1.0f / s;
        #pragma unroll
        for (int n = 0; n < NN; n++) swb[n*THREADS + tid] = ev[n] * inv;
    }

    // ---- epilogue: out[k] = sum_n w_n * sum_d A[n][d][k] diff[d] ----
    ull outp[8];
    #pragma unroll
    for (int q = 0; q < 8; q++) outp[q] = 0ULL;

    #pragma unroll 2
    for (int n = 0; n < NN; n++) {
        const ulonglong2* ap = reinterpret_cast<const ulonglong2*>(sA + n*DD*DD);
        ull pp[8];
        #pragma unroll
        for (int q = 0; q < 8; q++) pp[q] = 0ULL;

        #pragma unroll
        for (int d = 0; d < DD; d++) {
            ulonglong2 aA = ap[4*d + 0];
            ulonglong2 aB = ap[4*d + 1];
            ulonglong2 aC = ap[4*d + 2];
            ulonglong2 aD = ap[4*d + 3];
            const ull dv = diffd[d];
            pp[0] = fma2(aA.x, dv, pp[0]);
            pp[1] = fma2(aA.y, dv, pp[1]);
            pp[2] = fma2(aB.x, dv, pp[2]);
            pp[3] = fma2(aB.y, dv, pp[3]);
            pp[4] = fma2(aC.x, dv, pp[4]);
            pp[5] = fma2(aC.y, dv, pp[5]);
            pp[6] = fma2(aD.x, dv, pp[6]);
            pp[7] = fma2(aD.y, dv, pp[7]);
        }
        const ull wd = dup2(swb[n*THREADS + tid]);
        #pragma unroll
        for (int q = 0; q < 8; q++)
            outp[q] = fma2(wd, pp[q], outp[q]);
    }

    // ---- store (weights pre-normalized) ----
    {
        float4* o = reinterpret_cast<float4*>(out + (size_t)row * DD);
        #pragma unroll
        for (int q = 0; q < 4; q++) {
            float a, b, c, d;
            unpack2(outp[2*q],   a, b);
            unpack2(outp[2*q+1], c, d);
            o[q] = make_float4(a, b, c, d);
        }
    }
}

extern "C" void kernel_launch(void* const* d_in, const int* in_sizes, int n_in,
                              void* d_out, int out_size)
{
    const float* x_cur = (const float*)d_in[0];
    const float* W1    = (const float*)d_in[1];
    const float* b1    = (const float*)d_in[2];
    const float* W2    = (const float*)d_in[3];
    const float* b2    = (const float*)d_in[4];
    const float* Bm    = (const float*)d_in[5];
    const float* Cm    = (const float*)d_in[6];
    const float* xt    = (const float*)d_in[7];
    float* out = (float*)d_out;

    const int Btot = in_sizes[0] / DD;
    const size_t smem_bytes = (size_t)SMEM_FLOATS * sizeof(float);

    cudaFuncSetAttribute(fused_gated_ds_kernel,
                         cudaFuncAttributeMaxDynamicSharedMemorySize,
                         (int)smem_bytes);

    const int grid = (Btot + THREADS - 1) / THREADS;
    fused_gated_ds_kernel<<<grid, THREADS, smem_bytes>>>(
        x_cur, W1, b1, W2, b2, Bm, Cm, xt, out, Btot);
}